// round 13
// baseline (speedup 1.0000x reference)
#include <cuda_runtime.h>

// Problem constants
constexpr int kB = 512;   // batch
constexpr int kL = 128;   // seq len
constexpr int kD = 128;   // model dim
// H = 4 heads of 32
constexpr int kT  = 4;    // timesteps per fused block
constexpr int kNB = kL / kT;  // 32 blocks

// Scratch (device globals: allocation-free rule)
__device__ float    g_x [kB * kL * kD];               // residual stream, [b][t][d]
__device__ unsigned g_xn[kB * kL * kD];               // LN output, tf32 bit patterns
__device__ float    g_h [kB * kL * kD];               // raw scan output h
__device__ unsigned g_Wt[2 * 4 * kD * kD];            // W rounded to tf32

typedef unsigned long long ull;

__device__ __forceinline__ ull pack2(float lo, float hi) {
    ull r; asm("mov.b64 %0,{%1,%2};" : "=l"(r) : "f"(lo), "f"(hi)); return r;
}
__device__ __forceinline__ void unpack2(ull v, float& lo, float& hi) {
    asm("mov.b64 {%0,%1},%2;" : "=f"(lo), "=f"(hi) : "l"(v));
}
__device__ __forceinline__ ull ffma2(ull a, ull b, ull c) {
    ull d; asm("fma.rn.f32x2 %0,%1,%2,%3;" : "=l"(d) : "l"(a), "l"(b), "l"(c)); return d;
}
__device__ __forceinline__ float tanh_fast(float x) {
    float y; asm("tanh.approx.f32 %0,%1;" : "=f"(y) : "f"(x)); return y;
}
__device__ __forceinline__ unsigned to_tf32(float f) {
    unsigned u; asm("cvt.rna.tf32.f32 %0, %1;" : "=r"(u) : "f"(f)); return u;
}

__device__ __forceinline__ void cp_async16(unsigned smem, const void* gptr) {
    asm volatile("cp.async.cg.shared.global [%0], [%1], 16;" :: "r"(smem), "l"(gptr));
}
__device__ __forceinline__ void cp_commit() {
    asm volatile("cp.async.commit_group;");
}
template<int N>
__device__ __forceinline__ void cp_wait() {
    asm volatile("cp.async.wait_group %0;" :: "n"(N));
}

#define MMA_TF32(C0,C1,C2,C3, A0,A1,A2,A3, B0,B1)                              \
    asm volatile(                                                              \
        "mma.sync.aligned.m16n8k8.row.col.f32.tf32.tf32.f32 "                  \
        "{%0,%1,%2,%3}, {%4,%5,%6,%7}, {%8,%9}, {%0,%1,%2,%3};"                \
        : "+f"(C0), "+f"(C1), "+f"(C2), "+f"(C3)                               \
        : "r"(A0), "r"(A1), "r"(A2), "r"(A3), "r"(B0), "r"(B1))

// ---------------------------------------------------------------------------
// W -> tf32 pre-round (both layers, once per launch)
// ---------------------------------------------------------------------------
__global__ void k_wcvt(const float* __restrict__ Wg) {
    int i = blockIdx.x * 256 + threadIdx.x;
    #pragma unroll
    for (int j = 0; j < 4; j++) {
        int e = i * 4 + j;
        g_Wt[e] = to_tf32(__ldg(&Wg[e]));
    }
}

// ---------------------------------------------------------------------------
// Fused embedding gather + LayerNorm(layer0). One warp per row of 128.
// ---------------------------------------------------------------------------
__global__ void k_embed_ln(const int* __restrict__ ids, const float4* __restrict__ emb,
                           const float* __restrict__ w, const float* __restrict__ bb) {
    int t    = blockIdx.x * 256 + threadIdx.x;
    int row  = t >> 5;
    int lane = t & 31;
    int id   = __ldg(&ids[row]);
    float4 v = emb[(size_t)id * 32 + lane];
    ((float4*)g_x)[(size_t)row * 32 + lane] = v;
    float s = v.x + v.y + v.z + v.w;
    float q = v.x*v.x + v.y*v.y + v.z*v.z + v.w*v.w;
    #pragma unroll
    for (int o = 16; o; o >>= 1) {
        s += __shfl_xor_sync(0xffffffffu, s, o);
        q += __shfl_xor_sync(0xffffffffu, q, o);
    }
    float mu  = s * (1.f / 128.f);
    float var = fmaxf(q * (1.f / 128.f) - mu * mu, 0.f);
    float rs  = rsqrtf(var + 1e-5f);
    float4 wv = ((const float4*)w)[lane];
    float4 bv = ((const float4*)bb)[lane];
    uint4 o4;
    o4.x = to_tf32((v.x - mu) * rs * wv.x + bv.x);
    o4.y = to_tf32((v.y - mu) * rs * wv.y + bv.y);
    o4.z = to_tf32((v.z - mu) * rs * wv.z + bv.z);
    o4.w = to_tf32((v.w - mu) * rs * wv.w + bv.w);
    ((uint4*)g_xn)[(size_t)row * 32 + lane] = o4;
}

// ---------------------------------------------------------------------------
// Fused GroupNorm + residual (+ optional LayerNorm->tf32 for next layer).
// ---------------------------------------------------------------------------
template<bool DO_LN>
__global__ void k_gn(const float* __restrict__ gnw,
                     const float* __restrict__ lnw, const float* __restrict__ lnb) {
    const unsigned FULL = 0xffffffffu;
    int t    = blockIdx.x * 256 + threadIdx.x;
    int row  = t >> 5;
    int lane = t & 31;
    float4 hv = ((const float4*)g_h)[(size_t)row * 32 + lane];
    float4 xv = ((const float4*)g_x)[(size_t)row * 32 + lane];
    float s = hv.x + hv.y + hv.z + hv.w;
    float q = hv.x*hv.x + hv.y*hv.y + hv.z*hv.z + hv.w*hv.w;
    #pragma unroll
    for (int o = 1; o < 8; o <<= 1) {
        s += __shfl_xor_sync(FULL, s, o);
        q += __shfl_xor_sync(FULL, q, o);
    }
    float mu  = s * (1.f / 32.f);
    float var = fmaxf(q * (1.f / 32.f) - mu * mu, 0.f);
    float rs  = rsqrtf(var + 1e-5f);
    float4 gw = ((const float4*)gnw)[lane];
    float4 xp;
    xp.x = xv.x + (hv.x - mu) * rs * gw.x;
    xp.y = xv.y + (hv.y - mu) * rs * gw.y;
    xp.z = xv.z + (hv.z - mu) * rs * gw.z;
    xp.w = xv.w + (hv.w - mu) * rs * gw.w;
    ((float4*)g_x)[(size_t)row * 32 + lane] = xp;

    if (DO_LN) {
        float s2 = xp.x + xp.y + xp.z + xp.w;
        float q2 = xp.x*xp.x + xp.y*xp.y + xp.z*xp.z + xp.w*xp.w;
        #pragma unroll
        for (int o = 16; o; o >>= 1) {
            s2 += __shfl_xor_sync(FULL, s2, o);
            q2 += __shfl_xor_sync(FULL, q2, o);
        }
        float mu2  = s2 * (1.f / 128.f);
        float var2 = fmaxf(q2 * (1.f / 128.f) - mu2 * mu2, 0.f);
        float rs2  = rsqrtf(var2 + 1e-5f);
        float4 wv = ((const float4*)lnw)[lane];
        float4 bv = ((const float4*)lnb)[lane];
        uint4 o4;
        o4.x = to_tf32((xp.x - mu2) * rs2 * wv.x + bv.x);
        o4.y = to_tf32((xp.y - mu2) * rs2 * wv.y + bv.y);
        o4.z = to_tf32((xp.z - mu2) * rs2 * wv.z + bv.z);
        o4.w = to_tf32((xp.w - mu2) * rs2 * wv.w + bv.w);
        ((uint4*)g_xn)[(size_t)row * 32 + lane] = o4;
    }
}

// ---------------------------------------------------------------------------
// sLSTM gate math: 5 MUFU (3 ex2 + tanh + rcp)
// ---------------------------------------------------------------------------
__device__ __forceinline__ void gate_step(float ai, float af, float az, float ao,
                                          float& h, float& c, float& n, float& m) {
    float fm = af + m;
    float mn = fmaxf(fm, ai);
    float iv = __expf(ai - mn);
    float fv = __expf(fm - mn);
    float th = tanh_fast(az);
    c = fmaf(fv, c, iv * th);
    n = fmaf(fv, n, iv);
    float eo = __expf(-ao);                   // h = sigmoid(ao) * c / n
    float denom = fmaf(n, eo, n);             //   = c / (n * (1 + e^-ao))
    h = __fdividef(c, denom);
    m = mn;
}

// ---------------------------------------------------------------------------
// FUSED input-GEMM + recurrent scan. Grid 128 x 256, 4 batches/CTA.
// Scan body = round-11 (fma matvec, no per-step barriers). Between scan
// steps of block k, the 8 warps compute block k+1's preactivations with
// tensor-core mma (M=16: 4 batches x 4 timesteps; each warp owns 64 of the
// 512 gate columns). pre double-buffered in smem; xn triple-buffered via
// cp.async; W streamed from L2. One __syncthreads per 4 steps.
// ---------------------------------------------------------------------------
constexpr int XN_STR  = 132;                        // padded xn row (words)
constexpr int PRE_STR = 516;                        // padded pre row (words)
constexpr int FUS_SMEM = (3 * 16 * XN_STR + 2 * 4 * 4 * PRE_STR + 512 + 1024) * 4;

__global__ void __launch_bounds__(256, 1) k_fused(int layer,
                                                  const float* __restrict__ R,
                                                  const float* __restrict__ bias) {
    extern __shared__ float sm[];
    float* xn_s   = sm;                              // [3][16][XN_STR]
    float* pre_s  = sm + 3 * 16 * XN_STR;            // [2][4][4][PRE_STR]
    float* bias_s = pre_s + 2 * 4 * 4 * PRE_STR;     // [512]
    float* shA    = bias_s + 512;                    // [2][2][4][32]
    float* shB    = shA + 512;

    int tid  = threadIdx.x;
    int warp = tid >> 5, lane = tid & 31;
    int gid  = lane >> 2, tg = lane & 3;             // mma roles

    // scan roles
    int o    = tid & 127;
    int grp  = tid >> 7;
    int hh   = (tid >> 5) & 3;
    int bA   = grp * 2, bB = bA + 1;                 // CTA-local batches
    int b0   = blockIdx.x * 4 + bA;                  // global batch A

    // bias -> smem
    bias_s[tid]       = __ldg(&bias[tid]);
    bias_s[tid + 256] = __ldg(&bias[tid + 256]);

    // R in registers (round-11 layout)
    ull Rr2[64];
    #pragma unroll
    for (int g = 0; g < 4; g++)
        #pragma unroll
        for (int dp = 0; dp < 16; dp++) {
            float r0 = __ldg(&R[((g * 4 + hh) * 32 + 2 * dp)     * 32 + lane]);
            float r1 = __ldg(&R[((g * 4 + hh) * 32 + 2 * dp + 1) * 32 + lane]);
            Rr2[g * 16 + dp] = pack2(r0, r1);
        }

    const unsigned* WL = g_Wt + (size_t)layer * 4 * 128 * 128;
    unsigned xn_u = (unsigned)__cvta_generic_to_shared(xn_s);

    // cp.async one xn block (16 rows = 4 batches x 4 timesteps)
    auto issue_xn = [&](int blk) {
        int slot = blk % 3;
        #pragma unroll
        for (int i = 0; i < 2; i++) {
            int c = i * 256 + tid;                   // 512 chunks of 16B
            int r = c >> 5, cc = c & 31;
            int b = r & 3, dt = r >> 2;
            size_t grow = (size_t)(blockIdx.x * 4 + b) * 128 + blk * 4 + dt;
            cp_async16(xn_u + ((slot * 16 + r) * XN_STR + cc * 4) * 4,
                       g_xn + grow * 128 + cc * 4);
        }
        cp_commit();
    };

    float acc[8][4];
    auto seed_acc = [&]() {
        #pragma unroll
        for (int nt = 0; nt < 8; nt++) {
            float bz0 = bias_s[warp * 64 + nt * 8 + tg * 2];
            float bz1 = bias_s[warp * 64 + nt * 8 + tg * 2 + 1];
            acc[nt][0] = bz0; acc[nt][1] = bz1;
            acc[nt][2] = bz0; acc[nt][3] = bz1;
        }
    };

    // one quarter (4 k-tiles) of the mma work for block blk
    auto mma_quarter = [&](int blk, int q) {
        const float* xs = xn_s + (blk % 3) * 16 * XN_STR;
        #pragma unroll
        for (int kt = q * 4; kt < q * 4 + 4; kt++) {
            int k0 = kt * 8 + tg;
            unsigned a0 = __float_as_uint(xs[gid * XN_STR + k0]);
            unsigned a1 = __float_as_uint(xs[(gid + 8) * XN_STR + k0]);
            unsigned a2 = __float_as_uint(xs[gid * XN_STR + k0 + 4]);
            unsigned a3 = __float_as_uint(xs[(gid + 8) * XN_STR + k0 + 4]);
            unsigned bfr[8][2];
            #pragma unroll
            for (int nt = 0; nt < 8; nt++) {
                int n = warp * 64 + nt * 8 + gid;
                bfr[nt][0] = __ldg(&WL[n * 128 + k0]);
                bfr[nt][1] = __ldg(&WL[n * 128 + k0 + 4]);
            }
            #pragma unroll
            for (int nt = 0; nt < 8; nt++)
                MMA_TF32(acc[nt][0], acc[nt][1], acc[nt][2], acc[nt][3],
                         a0, a1, a2, a3, bfr[nt][0], bfr[nt][1]);
        }
    };

    auto store_acc = [&](int nbuf) {
        float* ps = pre_s + nbuf * 4 * 4 * PRE_STR;
        int dt0 = gid >> 2, bb = gid & 3;
        #pragma unroll
        for (int nt = 0; nt < 8; nt++) {
            int col = warp * 64 + nt * 8 + tg * 2;
            *(float2*)&ps[(dt0 * 4 + bb) * PRE_STR + col] =
                make_float2(acc[nt][0], acc[nt][1]);
            *(float2*)&ps[((dt0 + 2) * 4 + bb) * PRE_STR + col] =
                make_float2(acc[nt][2], acc[nt][3]);
        }
    };

    // scan state
    float hA = 0.f, cA = 0.f, nA = 0.f, mA = 0.f;
    float hB = 0.f, cB = 0.f, nB = 0.f, mB = 0.f;
    float* hoA = g_h + (size_t)b0 * kL * kD + o;
    float* hoB = hoA + (size_t)kL * kD;
    float* sA  = shA + (grp * 4 + hh) * 32;          // [slot][grp][hh][.] slot stride 256
    float* sB  = shB + (grp * 4 + hh) * 32;

    auto scan_step = [&](int buf, int dt, int tglob) {
        int s = tglob & 1;
        sA[s * 256 + lane] = hA;
        sB[s * 256 + lane] = hB;
        __syncwarp();

        const float* ps = pre_s + buf * 4 * 4 * PRE_STR + dt * 4 * PRE_STR;
        ull aiA = pack2(ps[bA * PRE_STR +       o], 0.f);
        ull afA = pack2(ps[bA * PRE_STR + 128 + o], 0.f);
        ull azA = pack2(ps[bA * PRE_STR + 256 + o], 0.f);
        ull aoA = pack2(ps[bA * PRE_STR + 384 + o], 0.f);
        ull aiB = pack2(ps[bB * PRE_STR +       o], 0.f);
        ull afB = pack2(ps[bB * PRE_STR + 128 + o], 0.f);
        ull azB = pack2(ps[bB * PRE_STR + 256 + o], 0.f);
        ull aoB = pack2(ps[bB * PRE_STR + 384 + o], 0.f);

        const float4* h4A = (const float4*)(sA + s * 256);
        const float4* h4B = (const float4*)(sB + s * 256);
        #pragma unroll
        for (int j = 0; j < 8; j++) {
            float4 va = h4A[j];
            float4 vb = h4B[j];
            ull a01 = pack2(va.x, va.y), a23 = pack2(va.z, va.w);
            ull b01 = pack2(vb.x, vb.y), b23 = pack2(vb.z, vb.w);
            int dp = 2 * j;
            aiA = ffma2(a01, Rr2[dp],      aiA); aiA = ffma2(a23, Rr2[dp + 1],      aiA);
            afA = ffma2(a01, Rr2[16 + dp], afA); afA = ffma2(a23, Rr2[16 + dp + 1], afA);
            azA = ffma2(a01, Rr2[32 + dp], azA); azA = ffma2(a23, Rr2[32 + dp + 1], azA);
            aoA = ffma2(a01, Rr2[48 + dp], aoA); aoA = ffma2(a23, Rr2[48 + dp + 1], aoA);
            aiB = ffma2(b01, Rr2[dp],      aiB); aiB = ffma2(b23, Rr2[dp + 1],      aiB);
            afB = ffma2(b01, Rr2[16 + dp], afB); afB = ffma2(b23, Rr2[16 + dp + 1], afB);
            azB = ffma2(b01, Rr2[32 + dp], azB); azB = ffma2(b23, Rr2[32 + dp + 1], azB);
            aoB = ffma2(b01, Rr2[48 + dp], aoB); aoB = ffma2(b23, Rr2[48 + dp + 1], aoB);
        }

        float lo, hi;
        unpack2(aiA, lo, hi); float gAi = lo + hi;
        unpack2(afA, lo, hi); float gAf = lo + hi;
        unpack2(azA, lo, hi); float gAz = lo + hi;
        unpack2(aoA, lo, hi); float gAo = lo + hi;
        unpack2(aiB, lo, hi); float gBi = lo + hi;
        unpack2(afB, lo, hi); float gBf = lo + hi;
        unpack2(azB, lo, hi); float gBz = lo + hi;
        unpack2(aoB, lo, hi); float gBo = lo + hi;

        gate_step(gAi, gAf, gAz, gAo, hA, cA, nA, mA);
        gate_step(gBi, gBf, gBz, gBo, hB, cB, nB, mB);

        hoA[(size_t)tglob * kD] = hA;
        hoB[(size_t)tglob * kD] = hB;
    };

    // ---- prologue: xn 0..2 in flight; compute block 0's pre ----
    issue_xn(0);
    issue_xn(1);
    issue_xn(2);
    cp_wait<1>();                                    // xn 0,1 ready
    __syncthreads();                                 // + bias_s visible
    seed_acc();
    mma_quarter(0, 0); mma_quarter(0, 1); mma_quarter(0, 2); mma_quarter(0, 3);
    store_acc(0);
    __syncthreads();                                 // pre_s[0] visible
    seed_acc();                                      // for block 1

    // ---- main loop: scan block blk while computing block blk+1's pre ----
    for (int blk = 0; blk < kNB; blk++) {
        int buf = blk & 1;
        if (blk + 3 < kNB) issue_xn(blk + 3);

        #pragma unroll
        for (int dt = 0; dt < kT; dt++) {
            scan_step(buf, dt, blk * kT + dt);
            if (blk + 1 < kNB) mma_quarter(blk + 1, dt);
        }

        cp_wait<1>();                                // xn[blk+2] ready
        if (blk + 1 < kNB) store_acc(buf ^ 1);
        __syncthreads();
        if (blk + 2 < kNB) seed_acc();
    }
}

// ---------------------------------------------------------------------------
// Head: mean over time, then 128->64 ReLU MLP, then 64->2
// ---------------------------------------------------------------------------
__global__ void k_head(const float* __restrict__ w1, const float* __restrict__ b1,
                       const float* __restrict__ w2, const float* __restrict__ b2,
                       float* __restrict__ out) {
    __shared__ float pooled[128];
    __shared__ float hid[64];
    int b = blockIdx.x, o = threadIdx.x;
    const float* xb = g_x + (size_t)b * kL * kD + o;
    float s = 0.f;
    #pragma unroll 8
    for (int t = 0; t < kL; t++) s += xb[(size_t)t * kD];
    pooled[o] = s * (1.f / 128.f);
    __syncthreads();
    if (o < 64) {
        float a = __ldg(&b1[o]);
        const float* wr = w1 + o * 128;
        #pragma unroll
        for (int d = 0; d < 128; d++) a = fmaf(pooled[d], __ldg(&wr[d]), a);
        hid[o] = fmaxf(a, 0.f);
    }
    __syncthreads();
    if (o < 2) {
        float a = __ldg(&b2[o]);
        const float* wr = w2 + o * 64;
        #pragma unroll
        for (int j = 0; j < 64; j++) a = fmaf(hid[j], __ldg(&wr[j]), a);
        out[b * 2 + o] = a;
    }
}

// ---------------------------------------------------------------------------
extern "C" void kernel_launch(void* const* d_in, const int* in_sizes, int n_in,
                              void* d_out, int out_size) {
    const int*   ids  = (const int*)  d_in[0];
    const float* emb  = (const float*)d_in[1];
    const float* ln_w = (const float*)d_in[2];
    const float* ln_b = (const float*)d_in[3];
    const float* Wg   = (const float*)d_in[4];
    const float* Rg   = (const float*)d_in[5];
    const float* bg   = (const float*)d_in[6];
    const float* gn_w = (const float*)d_in[7];
    const float* w1   = (const float*)d_in[8];
    const float* b1   = (const float*)d_in[9];
    const float* w2   = (const float*)d_in[10];
    const float* b2   = (const float*)d_in[11];
    float* out = (float*)d_out;

    cudaFuncSetAttribute(k_fused, cudaFuncAttributeMaxDynamicSharedMemorySize, FUS_SMEM);

    const int ROWS = kB * kL;                      // 65536 rows of 128

    k_wcvt<<<128, 256>>>(Wg);                      // both layers' W -> tf32
    k_embed_ln<<<ROWS / 8, 256>>>(ids, (const float4*)emb, ln_w, ln_b);

    // layer 0 (GEMM fused into scan)
    k_fused<<<128, 256, FUS_SMEM>>>(0, Rg, bg);
    k_gn<true><<<ROWS / 8, 256>>>(gn_w, ln_w + 128, ln_b + 128);

    // layer 1
    k_fused<<<128, 256, FUS_SMEM>>>(1, Rg + (size_t)4 * 4 * 32 * 32, bg + 512);
    k_gn<false><<<ROWS / 8, 256>>>(gn_w + 128, nullptr, nullptr);

    k_head<<<512, 128>>>(w1, b1, w2, b2, out);
}

// round 14
// speedup vs baseline: 2.0633x; 2.0633x over previous
#include <cuda_runtime.h>

// Problem constants
constexpr int kB = 512;   // batch
constexpr int kL = 128;   // seq len
constexpr int kD = 128;   // model dim
// H = 4 heads of 32

// Scratch (device globals: allocation-free rule)
__device__ float    g_x [kB * kL * kD];               // residual stream, [b][t][d]
__device__ unsigned g_xn[kB * kL * kD];               // LN output, tf32 bit patterns
__device__ float    g_h [kB * kL * kD];               // raw scan output h
__device__ float    g_pre[(size_t)kL * kB * 4 * kD];  // gate preacts, [t][b][g*128+d]
__device__ unsigned g_Wt[2 * 4 * kD * kD];            // W rounded to tf32

typedef unsigned long long ull;

__device__ __forceinline__ float tanh_fast(float x) {
    float y; asm("tanh.approx.f32 %0,%1;" : "=f"(y) : "f"(x)); return y;
}
__device__ __forceinline__ unsigned to_tf32(float f) {
    unsigned u; asm("cvt.rna.tf32.f32 %0, %1;" : "=r"(u) : "f"(f)); return u;
}
__device__ __forceinline__ float tf32f(float f) { return __uint_as_float(to_tf32(f)); }

__device__ __forceinline__ void cp_async16(unsigned smem, const void* gptr) {
    asm volatile("cp.async.cg.shared.global [%0], [%1], 16;" :: "r"(smem), "l"(gptr));
}
__device__ __forceinline__ void cp_commit() {
    asm volatile("cp.async.commit_group;");
}
template<int N>
__device__ __forceinline__ void cp_wait() {
    asm volatile("cp.async.wait_group %0;" :: "n"(N));
}

#define MMA_TF32(C0,C1,C2,C3, A0,A1,A2,A3, B0,B1)                              \
    asm volatile(                                                              \
        "mma.sync.aligned.m16n8k8.row.col.f32.tf32.tf32.f32 "                  \
        "{%0,%1,%2,%3}, {%4,%5,%6,%7}, {%8,%9}, {%0,%1,%2,%3};"                \
        : "+f"(C0), "+f"(C1), "+f"(C2), "+f"(C3)                               \
        : "r"(A0), "r"(A1), "r"(A2), "r"(A3), "r"(B0), "r"(B1))

// ---------------------------------------------------------------------------
// W -> tf32 pre-round (both layers, once per launch)
// ---------------------------------------------------------------------------
__global__ void k_wcvt(const float* __restrict__ Wg) {
    int i = blockIdx.x * 256 + threadIdx.x;
    #pragma unroll
    for (int j = 0; j < 4; j++) {
        int e = i * 4 + j;
        g_Wt[e] = to_tf32(__ldg(&Wg[e]));
    }
}

// ---------------------------------------------------------------------------
// Fused embedding gather + LayerNorm(layer0). One warp per row of 128.
// ---------------------------------------------------------------------------
__global__ void k_embed_ln(const int* __restrict__ ids, const float4* __restrict__ emb,
                           const float* __restrict__ w, const float* __restrict__ bb) {
    int t    = blockIdx.x * 256 + threadIdx.x;
    int row  = t >> 5;
    int lane = t & 31;
    int id   = __ldg(&ids[row]);
    float4 v = emb[(size_t)id * 32 + lane];
    ((float4*)g_x)[(size_t)row * 32 + lane] = v;
    float s = v.x + v.y + v.z + v.w;
    float q = v.x*v.x + v.y*v.y + v.z*v.z + v.w*v.w;
    #pragma unroll
    for (int o = 16; o; o >>= 1) {
        s += __shfl_xor_sync(0xffffffffu, s, o);
        q += __shfl_xor_sync(0xffffffffu, q, o);
    }
    float mu  = s * (1.f / 128.f);
    float var = fmaxf(q * (1.f / 128.f) - mu * mu, 0.f);
    float rs  = rsqrtf(var + 1e-5f);
    float4 wv = ((const float4*)w)[lane];
    float4 bv = ((const float4*)bb)[lane];
    uint4 o4;
    o4.x = to_tf32((v.x - mu) * rs * wv.x + bv.x);
    o4.y = to_tf32((v.y - mu) * rs * wv.y + bv.y);
    o4.z = to_tf32((v.z - mu) * rs * wv.z + bv.z);
    o4.w = to_tf32((v.w - mu) * rs * wv.w + bv.w);
    ((uint4*)g_xn)[(size_t)row * 32 + lane] = o4;
}

// ---------------------------------------------------------------------------
// Fused GroupNorm + residual (+ optional LayerNorm->tf32 for next layer).
// ---------------------------------------------------------------------------
template<bool DO_LN>
__global__ void k_gn(const float* __restrict__ gnw,
                     const float* __restrict__ lnw, const float* __restrict__ lnb) {
    const unsigned FULL = 0xffffffffu;
    int t    = blockIdx.x * 256 + threadIdx.x;
    int row  = t >> 5;
    int lane = t & 31;
    float4 hv = ((const float4*)g_h)[(size_t)row * 32 + lane];
    float4 xv = ((const float4*)g_x)[(size_t)row * 32 + lane];
    float s = hv.x + hv.y + hv.z + hv.w;
    float q = hv.x*hv.x + hv.y*hv.y + hv.z*hv.z + hv.w*hv.w;
    #pragma unroll
    for (int o = 1; o < 8; o <<= 1) {
        s += __shfl_xor_sync(FULL, s, o);
        q += __shfl_xor_sync(FULL, q, o);
    }
    float mu  = s * (1.f / 32.f);
    float var = fmaxf(q * (1.f / 32.f) - mu * mu, 0.f);
    float rs  = rsqrtf(var + 1e-5f);
    float4 gw = ((const float4*)gnw)[lane];
    float4 xp;
    xp.x = xv.x + (hv.x - mu) * rs * gw.x;
    xp.y = xv.y + (hv.y - mu) * rs * gw.y;
    xp.z = xv.z + (hv.z - mu) * rs * gw.z;
    xp.w = xv.w + (hv.w - mu) * rs * gw.w;
    ((float4*)g_x)[(size_t)row * 32 + lane] = xp;

    if (DO_LN) {
        float s2 = xp.x + xp.y + xp.z + xp.w;
        float q2 = xp.x*xp.x + xp.y*xp.y + xp.z*xp.z + xp.w*xp.w;
        #pragma unroll
        for (int o = 16; o; o >>= 1) {
            s2 += __shfl_xor_sync(FULL, s2, o);
            q2 += __shfl_xor_sync(FULL, q2, o);
        }
        float mu2  = s2 * (1.f / 128.f);
        float var2 = fmaxf(q2 * (1.f / 128.f) - mu2 * mu2, 0.f);
        float rs2  = rsqrtf(var2 + 1e-5f);
        float4 wv = ((const float4*)lnw)[lane];
        float4 bv = ((const float4*)lnb)[lane];
        uint4 o4;
        o4.x = to_tf32((xp.x - mu2) * rs2 * wv.x + bv.x);
        o4.y = to_tf32((xp.y - mu2) * rs2 * wv.y + bv.y);
        o4.z = to_tf32((xp.z - mu2) * rs2 * wv.z + bv.z);
        o4.w = to_tf32((xp.w - mu2) * rs2 * wv.w + bv.w);
        ((uint4*)g_xn)[(size_t)row * 32 + lane] = o4;
    }
}

// ---------------------------------------------------------------------------
// tf32 input GEMM (round-11): K tiled into 4 chunks of 32, double-buffered,
// __launch_bounds__(256,2) -> 2 CTAs/SM. grid (4, 512): bn = gate, bm = batch.
// ---------------------------------------------------------------------------
constexpr int GSTR = 36;
constexpr int GEMM_SMEM = 4 * 128 * GSTR * 4;

__global__ void __launch_bounds__(256, 2) k_gemm(int layer,
                                                 const float* __restrict__ bias) {
    extern __shared__ unsigned sh[];
    unsigned* As0 = sh;
    unsigned* As1 = sh + 128 * GSTR;
    unsigned* Bs0 = sh + 2 * 128 * GSTR;
    unsigned* Bs1 = sh + 3 * 128 * GSTR;

    int tid = threadIdx.x;
    int bn  = blockIdx.x;
    int bm  = blockIdx.y;

    const unsigned* Ag = g_xn + (size_t)bm * 128 * 128;
    const unsigned* Wg = g_Wt + (size_t)(layer * 4 + bn) * 128 * 128;
    unsigned As_u[2] = { (unsigned)__cvta_generic_to_shared(As0),
                         (unsigned)__cvta_generic_to_shared(As1) };
    unsigned Bs_u[2] = { (unsigned)__cvta_generic_to_shared(Bs0),
                         (unsigned)__cvta_generic_to_shared(Bs1) };

    auto issue = [&](int buf, int kc) {
        #pragma unroll
        for (int i = 0; i < 4; i++) {
            int e = i * 256 + tid, rr = e >> 3, cc = e & 7;
            cp_async16(As_u[buf] + (rr * GSTR + cc * 4) * 4,
                       Ag + rr * 128 + kc * 32 + cc * 4);
            cp_async16(Bs_u[buf] + (rr * GSTR + cc * 4) * 4,
                       Wg + rr * 128 + kc * 32 + cc * 4);
        }
        cp_commit();
    };
    issue(0, 0);
    issue(1, 1);

    int warp = tid >> 5, lane = tid & 31;
    int wm = warp >> 2, wn = warp & 3;
    int gid = lane >> 2, tg = lane & 3;

    float bz[4][2];
    #pragma unroll
    for (int j = 0; j < 4; j++) {
        int col = bn * 128 + wn * 32 + j * 8 + tg * 2;
        bz[j][0] = __ldg(&bias[col]);
        bz[j][1] = __ldg(&bias[col + 1]);
    }

    float acc[4][4][4];
    #pragma unroll
    for (int i = 0; i < 4; i++)
        #pragma unroll
        for (int j = 0; j < 4; j++)
            #pragma unroll
            for (int c = 0; c < 4; c++) acc[i][j][c] = 0.f;

    #pragma unroll
    for (int kc = 0; kc < 4; kc++) {
        unsigned* As = (kc & 1) ? As1 : As0;
        unsigned* Bs = (kc & 1) ? Bs1 : Bs0;
        if (kc < 3) cp_wait<1>(); else cp_wait<0>();
        __syncthreads();

        #pragma unroll
        for (int ks = 0; ks < 4; ks++) {
            int k0 = ks * 8 + tg;
            unsigned a[4][4], bf[4][2];
            #pragma unroll
            for (int i = 0; i < 4; i++) {
                int r0 = wm * 64 + i * 16 + gid;
                a[i][0] = As[r0 * GSTR + k0];
                a[i][1] = As[(r0 + 8) * GSTR + k0];
                a[i][2] = As[r0 * GSTR + k0 + 4];
                a[i][3] = As[(r0 + 8) * GSTR + k0 + 4];
            }
            #pragma unroll
            for (int j = 0; j < 4; j++) {
                int n0 = wn * 32 + j * 8 + gid;
                bf[j][0] = Bs[n0 * GSTR + k0];
                bf[j][1] = Bs[n0 * GSTR + k0 + 4];
            }
            #pragma unroll
            for (int i = 0; i < 4; i++)
                #pragma unroll
                for (int j = 0; j < 4; j++)
                    MMA_TF32(acc[i][j][0], acc[i][j][1], acc[i][j][2], acc[i][j][3],
                             a[i][0], a[i][1], a[i][2], a[i][3],
                             bf[j][0], bf[j][1]);
        }
        __syncthreads();

        if (kc + 2 < 4) issue(kc & 1, kc + 2);
    }

    #pragma unroll
    for (int i = 0; i < 4; i++) {
        int la = wm * 64 + i * 16 + gid;
        int lb = la + 8;
        float* outa = g_pre + ((size_t)la * 512 + bm) * 512;
        float* outb = g_pre + ((size_t)lb * 512 + bm) * 512;
        #pragma unroll
        for (int j = 0; j < 4; j++) {
            int col = bn * 128 + wn * 32 + j * 8 + tg * 2;
            *(float2*)&outa[col] = make_float2(acc[i][j][0] + bz[j][0], acc[i][j][1] + bz[j][1]);
            *(float2*)&outb[col] = make_float2(acc[i][j][2] + bz[j][0], acc[i][j][3] + bz[j][1]);
        }
    }
}

// ---------------------------------------------------------------------------
// sLSTM gate math: 5 MUFU (3 ex2 + tanh + rcp)
// ---------------------------------------------------------------------------
__device__ __forceinline__ void gate_step(float ai, float af, float az, float ao,
                                          float& h, float& c, float& n, float& m) {
    float fm = af + m;
    float mn = fmaxf(fm, ai);
    float iv = __expf(ai - mn);
    float fv = __expf(fm - mn);
    float th = tanh_fast(az);
    c = fmaf(fv, c, iv * th);
    n = fmaf(fv, n, iv);
    float eo = __expf(-ao);                   // h = sigmoid(ao) * c / n
    float denom = fmaf(n, eo, n);             //   = c / (n * (1 + e^-ao))
    h = __fdividef(c, denom);
    m = mn;
}

// ---------------------------------------------------------------------------
// Tensor-core recurrent scan v2. Grid 256 x 256, 2 batches/CTA,
// __launch_bounds__(256,2) -> 2 CTAs/SM (4 warps/SMSP cover mma latency).
// warp = (head hh, dim-half mhalf). M-tile = gate; B columns pack hi/lo:
// col 2b = tf32(h_b), col 2b+1 = tf32(h_b - tf32(h_b)). ONE mma pass gives
// hi-sums in c0/c2 and lo-sums in c1/c3; gate input = c0+c1 (exact split,
// 16 mma/step instead of 32). Lanes tg>=2 mirror batches 0/1 (no stores).
// One 64-thread named barrier per step per warp-pair.
// ---------------------------------------------------------------------------
__global__ void __launch_bounds__(256, 2) k_scan(const float* __restrict__ R) {
    __shared__ float sh_b[2][4][32][8];       // [slot][head][k(dim)][col]

    int tid   = threadIdx.x;
    int warp  = tid >> 5, lane = tid & 31;
    int hh    = warp >> 1;                    // head
    int mhalf = warp & 1;                     // dim half
    int gid   = lane >> 2, tg = lane & 3;

    bool active = (tg < 2);
    int bglob = blockIdx.x * 2 + (tg & 1);    // tg 2,3 mirror 0,1
    int dA    = mhalf * 16 + gid;
    int dB    = dA + 8;
    int oA    = hh * 32 + dA;
    int oB    = hh * 32 + dB;

    // zero smem (initial h = 0 everywhere)
    #pragma unroll
    for (int i = 0; i < 8; i++)
        ((float*)sh_b)[i * 256 + tid] = 0.f;

    // Stationary A fragments: A[r][k] = R[g][hh][k][d], rna tf32 (R12 layout)
    unsigned Af[4][4][4];
    #pragma unroll
    for (int g = 0; g < 4; g++)
        #pragma unroll
        for (int kt = 0; kt < 4; kt++) {
            int k0 = kt * 8 + tg;
            const float* Rb = R + ((size_t)(g * 4 + hh) * 32) * 32;
            Af[g][kt][0] = to_tf32(__ldg(&Rb[(k0)     * 32 + dA]));
            Af[g][kt][1] = to_tf32(__ldg(&Rb[(k0)     * 32 + dB]));
            Af[g][kt][2] = to_tf32(__ldg(&Rb[(k0 + 4) * 32 + dA]));
            Af[g][kt][3] = to_tf32(__ldg(&Rb[(k0 + 4) * 32 + dB]));
        }

    float cA = 0.f, nA = 0.f, mA = 0.f;
    float cB = 0.f, nB = 0.f, mB = 0.f;

    const float* pbase = g_pre + (size_t)bglob * 512;
    float preA[4], preB[4];
    #pragma unroll
    for (int g = 0; g < 4; g++) {
        preA[g] = pbase[g * 128 + oA];
        preB[g] = pbase[g * 128 + oB];
    }
    float* hoA = g_h + (size_t)bglob * kL * kD + oA;
    float* hoB = g_h + (size_t)bglob * kL * kD + oB;

    __syncthreads();                          // smem zeroing visible

    for (int t = 0; t < kL; t++) {
        int s = t & 1;

        // B fragments from smem (hi/lo interleaved in columns)
        unsigned bf[4][2];
        #pragma unroll
        for (int kt = 0; kt < 4; kt++) {
            int k0 = kt * 8 + tg;
            bf[kt][0] = __float_as_uint(sh_b[s][hh][k0][gid]);
            bf[kt][1] = __float_as_uint(sh_b[s][hh][k0 + 4][gid]);
        }

        // C seeded with the preactivations (hi slots); lo slots zero
        float C[4][4];
        #pragma unroll
        for (int g = 0; g < 4; g++) {
            C[g][0] = preA[g]; C[g][1] = 0.f;
            C[g][2] = preB[g]; C[g][3] = 0.f;
        }

        // prefetch next step's pre
        if (t + 1 < kL) {
            const float* pn = pbase + (size_t)(t + 1) * (kB * 512);
            #pragma unroll
            for (int g = 0; g < 4; g++) {
                preA[g] = pn[g * 128 + oA];
                preB[g] = pn[g * 128 + oB];
            }
        }

        // rec = R^T h : 16 mma (hi+lo in one pass via column packing)
        #pragma unroll
        for (int kt = 0; kt < 4; kt++)
            #pragma unroll
            for (int g = 0; g < 4; g++)
                MMA_TF32(C[g][0], C[g][1], C[g][2], C[g][3],
                         Af[g][kt][0], Af[g][kt][1], Af[g][kt][2], Af[g][kt][3],
                         bf[kt][0], bf[kt][1]);

        // gate math: gate value = hi-part + lo-part
        float hA, hB;
        gate_step(C[0][0] + C[0][1], C[1][0] + C[1][1],
                  C[2][0] + C[2][1], C[3][0] + C[3][1], hA, cA, nA, mA);
        gate_step(C[0][2] + C[0][3], C[1][2] + C[1][3],
                  C[2][2] + C[2][3], C[3][2] + C[3][3], hB, cB, nB, mB);

        int s2 = s ^ 1;
        if (active) {
            hoA[(size_t)t * kD] = hA;
            hoB[(size_t)t * kD] = hB;
            float hAhi = tf32f(hA), hBhi = tf32f(hB);
            sh_b[s2][hh][dA][2 * tg]     = hAhi;
            sh_b[s2][hh][dA][2 * tg + 1] = tf32f(hA - hAhi);
            sh_b[s2][hh][dB][2 * tg]     = hBhi;
            sh_b[s2][hh][dB][2 * tg + 1] = tf32f(hB - hBhi);
        }

        // pair barrier: warps (hh,0) and (hh,1) = 64 contiguous threads
        asm volatile("bar.sync %0, 64;" :: "r"(1 + hh) : "memory");
    }
}

// ---------------------------------------------------------------------------
// Head: mean over time, then 128->64 ReLU MLP, then 64->2
// ---------------------------------------------------------------------------
__global__ void k_head(const float* __restrict__ w1, const float* __restrict__ b1,
                       const float* __restrict__ w2, const float* __restrict__ b2,
                       float* __restrict__ out) {
    __shared__ float pooled[128];
    __shared__ float hid[64];
    int b = blockIdx.x, o = threadIdx.x;
    const float* xb = g_x + (size_t)b * kL * kD + o;
    float s = 0.f;
    #pragma unroll 8
    for (int t = 0; t < kL; t++) s += xb[(size_t)t * kD];
    pooled[o] = s * (1.f / 128.f);
    __syncthreads();
    if (o < 64) {
        float a = __ldg(&b1[o]);
        const float* wr = w1 + o * 128;
        #pragma unroll
        for (int d = 0; d < 128; d++) a = fmaf(pooled[d], __ldg(&wr[d]), a);
        hid[o] = fmaxf(a, 0.f);
    }
    __syncthreads();
    if (o < 2) {
        float a = __ldg(&b2[o]);
        const float* wr = w2 + o * 64;
        #pragma unroll
        for (int j = 0; j < 64; j++) a = fmaf(hid[j], __ldg(&wr[j]), a);
        out[b * 2 + o] = a;
    }
}

// ---------------------------------------------------------------------------
extern "C" void kernel_launch(void* const* d_in, const int* in_sizes, int n_in,
                              void* d_out, int out_size) {
    const int*   ids  = (const int*)  d_in[0];
    const float* emb  = (const float*)d_in[1];
    const float* ln_w = (const float*)d_in[2];
    const float* ln_b = (const float*)d_in[3];
    const float* Wg   = (const float*)d_in[4];
    const float* Rg   = (const float*)d_in[5];
    const float* bg   = (const float*)d_in[6];
    const float* gn_w = (const float*)d_in[7];
    const float* w1   = (const float*)d_in[8];
    const float* b1   = (const float*)d_in[9];
    const float* w2   = (const float*)d_in[10];
    const float* b2   = (const float*)d_in[11];
    float* out = (float*)d_out;

    cudaFuncSetAttribute(k_gemm, cudaFuncAttributeMaxDynamicSharedMemorySize, GEMM_SMEM);

    const int ROWS = kB * kL;                      // 65536 rows of 128

    k_wcvt<<<128, 256>>>(Wg);                      // both layers' W -> tf32
    k_embed_ln<<<ROWS / 8, 256>>>(ids, (const float4*)emb, ln_w, ln_b);

    // layer 0
    k_gemm<<<dim3(4, 512), 256, GEMM_SMEM>>>(0, bg);
    k_scan<<<256, 256>>>(Rg);
    k_gn<true><<<ROWS / 8, 256>>>(gn_w, ln_w + 128, ln_b + 128);

    // layer 1
    k_gemm<<<dim3(4, 512), 256, GEMM_SMEM>>>(1, bg + 512);
    k_scan<<<256, 256>>>(Rg + (size_t)4 * 4 * 32 * 32);
    k_gn<false><<<ROWS / 8, 256>>>(gn_w + 128, nullptr, nullptr);

    k_head<<<512, 128>>>(w1, b1, w2, b2, out);
}

// round 15
// speedup vs baseline: 2.1414x; 1.0378x over previous
#include <cuda_runtime.h>

// Problem constants
constexpr int kB = 512;   // batch
constexpr int kL = 128;   // seq len
constexpr int kD = 128;   // model dim
// H = 4 heads of 32
constexpr float LOG2E = 1.4426950408889634f;

// Scratch (device globals: allocation-free rule)
__device__ float    g_x [kB * kL * kD];               // residual stream, [b][t][d]
__device__ unsigned g_xn[kB * kL * kD];               // LN output, tf32 bit patterns
__device__ float    g_h [kB * kL * kD];               // raw scan output h
__device__ float    g_pre[(size_t)kL * kB * 4 * kD];  // gate preacts (i,f,o scaled by log2e)
__device__ unsigned g_Wt[2 * 4 * kD * kD];            // W -> tf32 (i,f,o rows pre-scaled)

typedef unsigned long long ull;

__device__ __forceinline__ ull pack2(float lo, float hi) {
    ull r; asm("mov.b64 %0,{%1,%2};" : "=l"(r) : "f"(lo), "f"(hi)); return r;
}
__device__ __forceinline__ void unpack2(ull v, float& lo, float& hi) {
    asm("mov.b64 {%0,%1},%2;" : "=f"(lo), "=f"(hi) : "l"(v));
}
__device__ __forceinline__ ull ffma2(ull a, ull b, ull c) {
    ull d; asm("fma.rn.f32x2 %0,%1,%2,%3;" : "=l"(d) : "l"(a), "l"(b), "l"(c)); return d;
}
__device__ __forceinline__ float tanh_fast(float x) {
    float y; asm("tanh.approx.f32 %0,%1;" : "=f"(y) : "f"(x)); return y;
}
__device__ __forceinline__ float ex2_fast(float x) {
    float y; asm("ex2.approx.f32 %0,%1;" : "=f"(y) : "f"(x)); return y;
}
__device__ __forceinline__ unsigned to_tf32(float f) {
    unsigned u; asm("cvt.rna.tf32.f32 %0, %1;" : "=r"(u) : "f"(f)); return u;
}

__device__ __forceinline__ void cp_async16(unsigned smem, const void* gptr) {
    asm volatile("cp.async.cg.shared.global [%0], [%1], 16;" :: "r"(smem), "l"(gptr));
}
__device__ __forceinline__ void cp_commit() {
    asm volatile("cp.async.commit_group;");
}
template<int N>
__device__ __forceinline__ void cp_wait() {
    asm volatile("cp.async.wait_group %0;" :: "n"(N));
}

#define MMA_TF32(C0,C1,C2,C3, A0,A1,A2,A3, B0,B1)                              \
    asm volatile(                                                              \
        "mma.sync.aligned.m16n8k8.row.col.f32.tf32.tf32.f32 "                  \
        "{%0,%1,%2,%3}, {%4,%5,%6,%7}, {%8,%9}, {%0,%1,%2,%3};"                \
        : "+f"(C0), "+f"(C1), "+f"(C2), "+f"(C3)                               \
        : "r"(A0), "r"(A1), "r"(A2), "r"(A3), "r"(B0), "r"(B1))

// ---------------------------------------------------------------------------
// W -> tf32 pre-round; gates i,f,o (g != 2) pre-scaled by log2e so the scan
// can use raw ex2 instead of exp.
// ---------------------------------------------------------------------------
__global__ void k_wcvt(const float* __restrict__ Wg) {
    int i = blockIdx.x * 256 + threadIdx.x;
    #pragma unroll
    for (int j = 0; j < 4; j++) {
        int e = i * 4 + j;
        int g = (e >> 14) & 3;                 // [l][g][128][128]
        float sc = (g == 2) ? 1.f : LOG2E;
        g_Wt[e] = to_tf32(__ldg(&Wg[e]) * sc);
    }
}

// ---------------------------------------------------------------------------
// Fused embedding gather + LayerNorm(layer0). One warp per row of 128.
// ---------------------------------------------------------------------------
__global__ void k_embed_ln(const int* __restrict__ ids, const float4* __restrict__ emb,
                           const float* __restrict__ w, const float* __restrict__ bb) {
    int t    = blockIdx.x * 256 + threadIdx.x;
    int row  = t >> 5;
    int lane = t & 31;
    int id   = __ldg(&ids[row]);
    float4 v = emb[(size_t)id * 32 + lane];
    ((float4*)g_x)[(size_t)row * 32 + lane] = v;
    float s = v.x + v.y + v.z + v.w;
    float q = v.x*v.x + v.y*v.y + v.z*v.z + v.w*v.w;
    #pragma unroll
    for (int o = 16; o; o >>= 1) {
        s += __shfl_xor_sync(0xffffffffu, s, o);
        q += __shfl_xor_sync(0xffffffffu, q, o);
    }
    float mu  = s * (1.f / 128.f);
    float var = fmaxf(q * (1.f / 128.f) - mu * mu, 0.f);
    float rs  = rsqrtf(var + 1e-5f);
    float4 wv = ((const float4*)w)[lane];
    float4 bv = ((const float4*)bb)[lane];
    uint4 o4;
    o4.x = to_tf32((v.x - mu) * rs * wv.x + bv.x);
    o4.y = to_tf32((v.y - mu) * rs * wv.y + bv.y);
    o4.z = to_tf32((v.z - mu) * rs * wv.z + bv.z);
    o4.w = to_tf32((v.w - mu) * rs * wv.w + bv.w);
    ((uint4*)g_xn)[(size_t)row * 32 + lane] = o4;
}

// ---------------------------------------------------------------------------
// Fused GroupNorm + residual (+ optional LayerNorm->tf32 for next layer).
// ---------------------------------------------------------------------------
template<bool DO_LN>
__global__ void k_gn(const float* __restrict__ gnw,
                     const float* __restrict__ lnw, const float* __restrict__ lnb) {
    const unsigned FULL = 0xffffffffu;
    int t    = blockIdx.x * 256 + threadIdx.x;
    int row  = t >> 5;
    int lane = t & 31;
    float4 hv = ((const float4*)g_h)[(size_t)row * 32 + lane];
    float4 xv = ((const float4*)g_x)[(size_t)row * 32 + lane];
    float s = hv.x + hv.y + hv.z + hv.w;
    float q = hv.x*hv.x + hv.y*hv.y + hv.z*hv.z + hv.w*hv.w;
    #pragma unroll
    for (int o = 1; o < 8; o <<= 1) {
        s += __shfl_xor_sync(FULL, s, o);
        q += __shfl_xor_sync(FULL, q, o);
    }
    float mu  = s * (1.f / 32.f);
    float var = fmaxf(q * (1.f / 32.f) - mu * mu, 0.f);
    float rs  = rsqrtf(var + 1e-5f);
    float4 gw = ((const float4*)gnw)[lane];
    float4 xp;
    xp.x = xv.x + (hv.x - mu) * rs * gw.x;
    xp.y = xv.y + (hv.y - mu) * rs * gw.y;
    xp.z = xv.z + (hv.z - mu) * rs * gw.z;
    xp.w = xv.w + (hv.w - mu) * rs * gw.w;
    ((float4*)g_x)[(size_t)row * 32 + lane] = xp;

    if (DO_LN) {
        float s2 = xp.x + xp.y + xp.z + xp.w;
        float q2 = xp.x*xp.x + xp.y*xp.y + xp.z*xp.z + xp.w*xp.w;
        #pragma unroll
        for (int o = 16; o; o >>= 1) {
            s2 += __shfl_xor_sync(FULL, s2, o);
            q2 += __shfl_xor_sync(FULL, q2, o);
        }
        float mu2  = s2 * (1.f / 128.f);
        float var2 = fmaxf(q2 * (1.f / 128.f) - mu2 * mu2, 0.f);
        float rs2  = rsqrtf(var2 + 1e-5f);
        float4 wv = ((const float4*)lnw)[lane];
        float4 bv = ((const float4*)lnb)[lane];
        uint4 o4;
        o4.x = to_tf32((xp.x - mu2) * rs2 * wv.x + bv.x);
        o4.y = to_tf32((xp.y - mu2) * rs2 * wv.y + bv.y);
        o4.z = to_tf32((xp.z - mu2) * rs2 * wv.z + bv.z);
        o4.w = to_tf32((xp.w - mu2) * rs2 * wv.w + bv.w);
        ((uint4*)g_xn)[(size_t)row * 32 + lane] = o4;
    }
}

// ---------------------------------------------------------------------------
// Persistent tf32 GEMM. grid (4, 74) = 296 CTAs = 2/SM, one wave.
// B (this gate's full W tile, 64 KB) loaded ONCE per CTA and resident; A
// streamed in 16 KB K-chunks (2-stage cp.async) continuously across the
// CTA's ~7 tiles, so epilogue stores overlap the next tile's loads.
// ---------------------------------------------------------------------------
constexpr int GSTR = 36;
constexpr int GEMM_SMEM = 6 * 128 * GSTR * 4;   // B 4 chunks + A 2 bufs = 110592

__global__ void __launch_bounds__(256, 2) k_gemm(int layer,
                                                 const float* __restrict__ bias) {
    extern __shared__ unsigned sh[];
    unsigned* Bs  = sh;                          // [4][128][GSTR]
    unsigned* As0 = sh + 4 * 128 * GSTR;
    unsigned* As1 = As0 + 128 * GSTR;

    int tid = threadIdx.x;
    int bn  = blockIdx.x;                        // gate
    int by  = blockIdx.y;                        // 0..73
    int ntile = (585 - by) / 74;                 // 6 or 7 tiles
    int nchunk = ntile * 4;

    const unsigned* Wg = g_Wt + (size_t)(layer * 4 + bn) * 128 * 128;
    unsigned As_u[2] = { (unsigned)__cvta_generic_to_shared(As0),
                         (unsigned)__cvta_generic_to_shared(As1) };
    unsigned Bs_u = (unsigned)__cvta_generic_to_shared(Bs);

    // A chunk for global chunk index gidx (tile = by + 74*(gidx>>2), kc = gidx&3)
    auto issueA = [&](int gidx) {
        if (gidx < nchunk) {
            int bm = by + 74 * (gidx >> 2);
            int kc = gidx & 3;
            const unsigned* Ag = g_xn + (size_t)bm * 128 * 128;
            unsigned dst = As_u[gidx & 1];
            #pragma unroll
            for (int i = 0; i < 4; i++) {
                int e = i * 256 + tid, rr = e >> 3, cc = e & 7;
                cp_async16(dst + (rr * GSTR + cc * 4) * 4,
                           Ag + rr * 128 + kc * 32 + cc * 4);
            }
        }
        cp_commit();                             // commit every call (group accounting)
    };

    // prologue: B (all 4 chunks, resident) + A chunk 0 as group 0; A chunk 1 as group 1
    #pragma unroll
    for (int kc = 0; kc < 4; kc++)
        #pragma unroll
        for (int i = 0; i < 4; i++) {
            int e = i * 256 + tid, rr = e >> 3, cc = e & 7;
            cp_async16(Bs_u + ((kc * 128 + rr) * GSTR + cc * 4) * 4,
                       Wg + rr * 128 + kc * 32 + cc * 4);
        }
    issueA(0);                                   // group 0 (B + A0)
    issueA(1);                                   // group 1

    int warp = tid >> 5, lane = tid & 31;
    int wm = warp >> 2, wn = warp & 3;
    int gid = lane >> 2, tg = lane & 3;

    float bsc = (bn == 2) ? 1.f : LOG2E;         // log2-domain gates i,f,o
    float bz[4][2];
    #pragma unroll
    for (int j = 0; j < 4; j++) {
        int col = bn * 128 + wn * 32 + j * 8 + tg * 2;
        bz[j][0] = __ldg(&bias[col]) * bsc;
        bz[j][1] = __ldg(&bias[col + 1]) * bsc;
    }

    float acc[4][4][4];
    #pragma unroll
    for (int i = 0; i < 4; i++)
        #pragma unroll
        for (int j = 0; j < 4; j++) {
            acc[i][j][0] = bz[j][0]; acc[i][j][1] = bz[j][1];
            acc[i][j][2] = bz[j][0]; acc[i][j][3] = bz[j][1];
        }

    for (int g = 0; g < nchunk; g++) {
        int kc = g & 3;
        cp_wait<1>();                            // A(g) done, A(g+1) may fly
        __syncthreads();

        unsigned* As  = (g & 1) ? As1 : As0;
        unsigned* Bsk = Bs + kc * 128 * GSTR;

        #pragma unroll
        for (int ks = 0; ks < 4; ks++) {
            int k0 = ks * 8 + tg;
            unsigned a[4][4], bf[4][2];
            #pragma unroll
            for (int i = 0; i < 4; i++) {
                int r0 = wm * 64 + i * 16 + gid;
                a[i][0] = As[r0 * GSTR + k0];
                a[i][1] = As[(r0 + 8) * GSTR + k0];
                a[i][2] = As[r0 * GSTR + k0 + 4];
                a[i][3] = As[(r0 + 8) * GSTR + k0 + 4];
            }
            #pragma unroll
            for (int j = 0; j < 4; j++) {
                int n0 = wn * 32 + j * 8 + gid;
                bf[j][0] = Bsk[n0 * GSTR + k0];
                bf[j][1] = Bsk[n0 * GSTR + k0 + 4];
            }
            #pragma unroll
            for (int i = 0; i < 4; i++)
                #pragma unroll
                for (int j = 0; j < 4; j++)
                    MMA_TF32(acc[i][j][0], acc[i][j][1], acc[i][j][2], acc[i][j][3],
                             a[i][0], a[i][1], a[i][2], a[i][3],
                             bf[j][0], bf[j][1]);
        }
        __syncthreads();                         // A buffer free before refill
        issueA(g + 2);

        if (kc == 3) {
            // epilogue for this tile (overlaps next tile's in-flight loads)
            int bm = by + 74 * (g >> 2);
            #pragma unroll
            for (int i = 0; i < 4; i++) {
                int la = wm * 64 + i * 16 + gid;
                int lb = la + 8;
                float* outa = g_pre + ((size_t)la * 512 + bm) * 512;
                float* outb = g_pre + ((size_t)lb * 512 + bm) * 512;
                #pragma unroll
                for (int j = 0; j < 4; j++) {
                    int col = bn * 128 + wn * 32 + j * 8 + tg * 2;
                    *(float2*)&outa[col] = make_float2(acc[i][j][0], acc[i][j][1]);
                    *(float2*)&outb[col] = make_float2(acc[i][j][2], acc[i][j][3]);
                }
            }
            // reseed accumulators with bias for the next tile
            #pragma unroll
            for (int i = 0; i < 4; i++)
                #pragma unroll
                for (int j = 0; j < 4; j++) {
                    acc[i][j][0] = bz[j][0]; acc[i][j][1] = bz[j][1];
                    acc[i][j][2] = bz[j][0]; acc[i][j][3] = bz[j][1];
                }
        }
    }
}

// ---------------------------------------------------------------------------
// sLSTM gate math, log2 domain for i,f,o (inputs pre-scaled by log2e):
// 4 raw EX2/tanh MUFU + 1 rcp.
// ---------------------------------------------------------------------------
__device__ __forceinline__ void gate_step(float ai, float af, float az, float ao,
                                          float& h, float& c, float& n, float& m) {
    float fm = af + m;
    float mn = fmaxf(fm, ai);
    float iv = ex2_fast(ai - mn);
    float fv = ex2_fast(fm - mn);
    float th = tanh_fast(az);
    c = fmaf(fv, c, iv * th);
    n = fmaf(fv, n, iv);
    float eo = ex2_fast(-ao);                 // sigmoid(x) = 1/(1+2^-(x*log2e))
    float denom = fmaf(n, eo, n);
    h = __fdividef(c, denom);
    m = mn;
}

// ---------------------------------------------------------------------------
// Recurrent sLSTM scan (round-11 body, best measured). Grid 128 x 256,
// 4 batches/CTA, thread = (batch-pair, o), warp = head. h broadcast through
// SMEM, no barriers. R rows for gates i,f,o pre-scaled by log2e.
// ---------------------------------------------------------------------------
__global__ void __launch_bounds__(256, 1) k_scan(const float* __restrict__ R) {
    __shared__ float shA[2][2][4][32];        // [slot][grp][head][d]
    __shared__ float shB[2][2][4][32];

    int o    = threadIdx.x & 127;            // output dim
    int grp  = threadIdx.x >> 7;             // batch pair within CTA
    int hh   = (threadIdx.x >> 5) & 3;       // head
    int lane = threadIdx.x & 31;

    int b0 = blockIdx.x * 4 + grp * 2;       // batch A; batch B = b0+1

    ull Rr2[64];
    #pragma unroll
    for (int g = 0; g < 4; g++) {
        float sc = (g == 2) ? 1.f : LOG2E;
        #pragma unroll
        for (int dp = 0; dp < 16; dp++) {
            float r0 = __ldg(&R[((g * 4 + hh) * 32 + 2 * dp)     * 32 + lane]) * sc;
            float r1 = __ldg(&R[((g * 4 + hh) * 32 + 2 * dp + 1) * 32 + lane]) * sc;
            Rr2[g * 16 + dp] = pack2(r0, r1);
        }
    }

    float hA = 0.f, cA = 0.f, nA = 0.f, mA = 0.f;
    float hB = 0.f, cB = 0.f, nB = 0.f, mB = 0.f;

    const float* pA = g_pre + (size_t)b0 * 512 + o;
    const float* pB = pA + 512;
    float* hoA = g_h + (size_t)b0 * kL * kD + o;
    float* hoB = hoA + (size_t)kL * kD;

    float a0 = pA[0], a1 = pA[128], a2 = pA[256], a3 = pA[384];
    float q0 = pB[0], q1 = pB[128], q2 = pB[256], q3 = pB[384];

    for (int t = 0; t < kL; t++) {
        int s = t & 1;
        shA[s][grp][hh][lane] = hA;
        shB[s][grp][hh][lane] = hB;
        __syncwarp();

        // accumulators carry the preactivation in the low half
        ull aiA = pack2(a0, 0.f), afA = pack2(a1, 0.f);
        ull azA = pack2(a2, 0.f), aoA = pack2(a3, 0.f);
        ull aiB = pack2(q0, 0.f), afB = pack2(q1, 0.f);
        ull azB = pack2(q2, 0.f), aoB = pack2(q3, 0.f);

        if (t + 1 < kL) {
            const float* nA_ = pA + (size_t)(t + 1) * (kB * 512);
            const float* nB_ = pB + (size_t)(t + 1) * (kB * 512);
            a0 = nA_[0]; a1 = nA_[128]; a2 = nA_[256]; a3 = nA_[384];
            q0 = nB_[0]; q1 = nB_[128]; q2 = nB_[256]; q3 = nB_[384];
        }

        const float4* h4A = (const float4*)shA[s][grp][hh];
        const float4* h4B = (const float4*)shB[s][grp][hh];
        #pragma unroll
        for (int j = 0; j < 8; j++) {
            float4 va = h4A[j];
            float4 vb = h4B[j];
            ull a01 = pack2(va.x, va.y), a23 = pack2(va.z, va.w);
            ull b01 = pack2(vb.x, vb.y), b23 = pack2(vb.z, vb.w);
            int dp = 2 * j;
            aiA = ffma2(a01, Rr2[dp],      aiA); aiA = ffma2(a23, Rr2[dp + 1],      aiA);
            afA = ffma2(a01, Rr2[16 + dp], afA); afA = ffma2(a23, Rr2[16 + dp + 1], afA);
            azA = ffma2(a01, Rr2[32 + dp], azA); azA = ffma2(a23, Rr2[32 + dp + 1], azA);
            aoA = ffma2(a01, Rr2[48 + dp], aoA); aoA = ffma2(a23, Rr2[48 + dp + 1], aoA);
            aiB = ffma2(b01, Rr2[dp],      aiB); aiB = ffma2(b23, Rr2[dp + 1],      aiB);
            afB = ffma2(b01, Rr2[16 + dp], afB); afB = ffma2(b23, Rr2[16 + dp + 1], afB);
            azB = ffma2(b01, Rr2[32 + dp], azB); azB = ffma2(b23, Rr2[32 + dp + 1], azB);
            aoB = ffma2(b01, Rr2[48 + dp], aoB); aoB = ffma2(b23, Rr2[48 + dp + 1], aoB);
        }

        float lo, hi;
        unpack2(aiA, lo, hi); float gAi = lo + hi;
        unpack2(afA, lo, hi); float gAf = lo + hi;
        unpack2(azA, lo, hi); float gAz = lo + hi;
        unpack2(aoA, lo, hi); float gAo = lo + hi;
        unpack2(aiB, lo, hi); float gBi = lo + hi;
        unpack2(afB, lo, hi); float gBf = lo + hi;
        unpack2(azB, lo, hi); float gBz = lo + hi;
        unpack2(aoB, lo, hi); float gBo = lo + hi;

        gate_step(gAi, gAf, gAz, gAo, hA, cA, nA, mA);
        gate_step(gBi, gBf, gBz, gBo, hB, cB, nB, mB);

        hoA[(size_t)t * kD] = hA;
        hoB[(size_t)t * kD] = hB;
    }
}

// ---------------------------------------------------------------------------
// Head: mean over time, then 128->64 ReLU MLP, then 64->2
// ---------------------------------------------------------------------------
__global__ void k_head(const float* __restrict__ w1, const float* __restrict__ b1,
                       const float* __restrict__ w2, const float* __restrict__ b2,
                       float* __restrict__ out) {
    __shared__ float pooled[128];
    __shared__ float hid[64];
    int b = blockIdx.x, o = threadIdx.x;
    const float* xb = g_x + (size_t)b * kL * kD + o;
    float s = 0.f;
    #pragma unroll 8
    for (int t = 0; t < kL; t++) s += xb[(size_t)t * kD];
    pooled[o] = s * (1.f / 128.f);
    __syncthreads();
    if (o < 64) {
        float a = __ldg(&b1[o]);
        const float* wr = w1 + o * 128;
        #pragma unroll
        for (int d = 0; d < 128; d++) a = fmaf(pooled[d], __ldg(&wr[d]), a);
        hid[o] = fmaxf(a, 0.f);
    }
    __syncthreads();
    if (o < 2) {
        float a = __ldg(&b2[o]);
        const float* wr = w2 + o * 64;
        #pragma unroll
        for (int j = 0; j < 64; j++) a = fmaf(hid[j], __ldg(&wr[j]), a);
        out[b * 2 + o] = a;
    }
}

// ---------------------------------------------------------------------------
extern "C" void kernel_launch(void* const* d_in, const int* in_sizes, int n_in,
                              void* d_out, int out_size) {
    const int*   ids  = (const int*)  d_in[0];
    const float* emb  = (const float*)d_in[1];
    const float* ln_w = (const float*)d_in[2];
    const float* ln_b = (const float*)d_in[3];
    const float* Wg   = (const float*)d_in[4];
    const float* Rg   = (const float*)d_in[5];
    const float* bg   = (const float*)d_in[6];
    const float* gn_w = (const float*)d_in[7];
    const float* w1   = (const float*)d_in[8];
    const float* b1   = (const float*)d_in[9];
    const float* w2   = (const float*)d_in[10];
    const float* b2   = (const float*)d_in[11];
    float* out = (float*)d_out;

    cudaFuncSetAttribute(k_gemm, cudaFuncAttributeMaxDynamicSharedMemorySize, GEMM_SMEM);

    const int ROWS = kB * kL;                      // 65536 rows of 128

    k_wcvt<<<128, 256>>>(Wg);                      // both layers' W -> tf32 (scaled)
    k_embed_ln<<<ROWS / 8, 256>>>(ids, (const float4*)emb, ln_w, ln_b);

    // layer 0
    k_gemm<<<dim3(4, 74), 256, GEMM_SMEM>>>(0, bg);
    k_scan<<<128, 256>>>(Rg);
    k_gn<true><<<ROWS / 8, 256>>>(gn_w, ln_w + 128, ln_b + 128);

    // layer 1
    k_gemm<<<dim3(4, 74), 256, GEMM_SMEM>>>(1, bg + 512);
    k_scan<<<128, 256>>>(Rg + (size_t)4 * 4 * 32 * 32);
    k_gn<false><<<ROWS / 8, 256>>>(gn_w + 128, nullptr, nullptr);

    k_head<<<512, 128>>>(w1, b1, w2, b2, out);
}